// round 9
// baseline (speedup 1.0000x reference)
#include <cuda_runtime.h>
#include <cstdint>

// SwappingCorruption: out[i,j] = mask[i,j] ? x[i, perm[i,j]] : x[i,j]
// B=16384 rows, F=2048 cols, fp32; mask/perm int32.
//
// R8 analysis: DRAM-bound at 86% busy, ~508 MB total (x 128 + mask 128 +
// out 128 + perm ~124 at 64B DRAM granularity). Bytes are near the floor,
// so this round removes the utilization leak instead: no SMEM staging, no
// __syncthreads. The gather x[row, p] is served by L2/MSHR-merge with the
// coalesced row read of the same CTA (same 8 KB row, L2 is 126 MB) — no
// extra DRAM traffic. Identity values stay in registers. All warps stream
// independently: front-batched 4x LDG.128 (v0,v1,m0,m1), conditional perm
// int4 + scalar gathers, stores.

static constexpr int N_FEAT  = 2048;
static constexpr int THREADS = 256;

__global__ __launch_bounds__(THREADS)
void swap_corruption_kernel(const float* __restrict__ x,
                            const int*   __restrict__ mask,
                            const int*   __restrict__ perm,
                            float* __restrict__ out)
{
    const size_t base = (size_t)blockIdx.x * N_FEAT;
    const float*  xrow = x + base;
    const float4* xr   = reinterpret_cast<const float4*>(xrow);
    const int4*   mr   = reinterpret_cast<const int4*>(mask + base);
    const int4*   pr   = reinterpret_cast<const int4*>(perm + base);
    float4*       owr  = reinterpret_cast<float4*>(out + base);

    const int i0 = threadIdx.x;
    const int i1 = threadIdx.x + THREADS;

    // Front-batch all streaming loads (MLP_p1 = 4 LDG.128).
    float4 v0 = xr[i0];
    float4 v1 = xr[i1];
    int4   m0 = mr[i0];
    int4   m1 = mr[i1];

    // Quad 0: gather from the same row via L2 (sectors hot from xr reads).
    if (m0.x | m0.y | m0.z | m0.w) {
        const int4 p = pr[i0];
        if (m0.x) v0.x = __ldg(xrow + p.x);
        if (m0.y) v0.y = __ldg(xrow + p.y);
        if (m0.z) v0.z = __ldg(xrow + p.z);
        if (m0.w) v0.w = __ldg(xrow + p.w);
    }
    // Quad 1
    if (m1.x | m1.y | m1.z | m1.w) {
        const int4 p = pr[i1];
        if (m1.x) v1.x = __ldg(xrow + p.x);
        if (m1.y) v1.y = __ldg(xrow + p.y);
        if (m1.z) v1.z = __ldg(xrow + p.z);
        if (m1.w) v1.w = __ldg(xrow + p.w);
    }

    owr[i0] = v0;
    owr[i1] = v1;
}

extern "C" void kernel_launch(void* const* d_in, const int* in_sizes, int n_in,
                              void* d_out, int out_size)
{
    // metadata order: x (float32), swap_mask (int32 0/1), perm (int32)
    const float* x    = (const float*)d_in[0];
    const int*   mask = (const int*)d_in[1];
    const int*   perm = (const int*)d_in[2];
    float*       out  = (float*)d_out;

    const int batch = in_sizes[0] / N_FEAT;  // 16384
    swap_corruption_kernel<<<batch, THREADS>>>(x, mask, perm, out);
}